// round 14
// baseline (speedup 1.0000x reference)
#include <cuda_runtime.h>
#include <math.h>

// ---------------- scratch (static __device__, allocation-free) ----------------
__device__ float g_y0 [256 * 64 * 624];     // conv block 0 out (b,c,p); reused as layer1 hs
__device__ float g_seq[77 * 256 * 128];     // conv block 1 out, (t,b,c)
__device__ float g_xp [77 * 256 * 1024];    // lstm input projection (t,b,4H), reused per layer
__device__ float g_hs0[77 * 256 * 256];     // layer0 hidden sequence (t,b,H)
__device__ float g_f1 [256 * 512];
__device__ float g_f2 [256 * 512];
__device__ unsigned g_cnt[8];               // per-batch-tile arrival counters

// SG(11,3) interior smoothing taps (symmetric): [-36,9,44,69,84,89,84,69,44,9,-36]/429
__constant__ float c_sg[11] = {
    -36.f/429.f, 9.f/429.f, 44.f/429.f, 69.f/429.f, 84.f/429.f, 89.f/429.f,
    84.f/429.f, 69.f/429.f, 44.f/429.f, 9.f/429.f, -36.f/429.f };

// ---------------- f32x2 packed-math helpers ----------------
__device__ __forceinline__ unsigned long long pk2(float a, float b) {
    unsigned long long r;
    asm("mov.b64 %0, {%1, %2};" : "=l"(r) : "f"(a), "f"(b));
    return r;
}
__device__ __forceinline__ void fma2(unsigned long long& d,
                                     unsigned long long a, unsigned long long b) {
    asm("fma.rn.f32x2 %0, %1, %2, %0;" : "+l"(d) : "l"(a), "l"(b));
}
__device__ __forceinline__ float2 upk(unsigned long long v) {
    float2 r;
    asm("mov.b64 {%0, %1}, %2;" : "=f"(r.x), "=f"(r.y) : "l"(v));
    return r;
}

// ---------------- savgol edge fit (cols 0..4 only; high edge is never consumed) ----------------
__device__ __forceinline__ void sg_fit(const float* __restrict__ xw, double a[4]) {
    double m0 = 0, m1 = 0, m2 = 0, m3 = 0;
    #pragma unroll
    for (int w = 0; w < 11; w++) {
        double y = (double)xw[w]; double t = (double)w;
        m0 += y; m1 += y * t; m2 += y * t * t; m3 += y * t * t * t;
    }
    double M[4][5] = {
        {11.0,    55.0,     385.0,     3025.0,    m0},
        {55.0,    385.0,    3025.0,    25333.0,   m1},
        {385.0,   3025.0,   25333.0,   220825.0,  m2},
        {3025.0,  25333.0,  220825.0,  1978405.0, m3}};
    #pragma unroll
    for (int i = 0; i < 4; i++) {
        double p = M[i][i];
        #pragma unroll
        for (int j = i; j < 5; j++) M[i][j] /= p;
        #pragma unroll
        for (int r = 0; r < 4; r++) {
            if (r != i) {
                double f = M[r][i];
                #pragma unroll
                for (int j = i; j < 5; j++) M[r][j] -= f * M[i][j];
            }
        }
    }
    a[0] = M[0][4]; a[1] = M[1][4]; a[2] = M[2][4]; a[3] = M[3][4];
}

// ---------------- conv block 0 (savgol fused in; also resets lstm counters) ----------------
__global__ __launch_bounds__(256) void conv0_kernel(
    const float* __restrict__ x,
    const float* __restrict__ w, const float* __restrict__ bias,
    const float* __restrict__ bg, const float* __restrict__ bb,
    const float* __restrict__ bm, const float* __restrict__ bv) {
    __shared__ float xs[2080];
    __shared__ float in_s[2064];
    __shared__ float ws[64][17];
    __shared__ float scs[64], shs[64], bss[64];
    int b = blockIdx.y;
    int p0 = blockIdx.x * 128;
    int tid = threadIdx.x;
    if (blockIdx.x == 0 && blockIdx.y == 0 && tid < 8) g_cnt[tid] = 0;
    int base = 16 * p0;
    const float* xr = x + (size_t)b * 10000;
    for (int i = tid; i < 2074; i += 256) {
        int col = base - 5 + i;
        xs[i] = (col >= 0 && col < 10000) ? xr[col] : 0.f;
    }
    for (int i = tid; i < 1024; i += 256) ws[i >> 4][i & 15] = w[i];
    if (tid < 64) {
        float sc = bg[tid] * rsqrtf(bv[tid] + 1e-5f);
        scs[tid] = sc;
        shs[tid] = bb[tid] - bm[tid] * sc;
        bss[tid] = bias[tid];
    }
    __syncthreads();
    for (int i = tid; i < 2064; i += 256) {
        float acc = 0.f;
        #pragma unroll
        for (int j = 0; j < 11; j++) acc = fmaf(xs[i + j], c_sg[j], acc);
        in_s[i] = acc;
    }
    if (blockIdx.x == 0 && tid < 5) {
        double a[4]; sg_fit(xs + 5, a);
        double t = (double)tid;
        in_s[tid] = (float)(a[0] + t * (a[1] + t * (a[2] + t * a[3])));
    }
    __syncthreads();
    int p = p0 + (tid & 127);
    int cb = (tid >> 7) * 32;
    if (p >= 624) return;
    float xv[24];
    int lb = 16 * (tid & 127);
    #pragma unroll
    for (int k = 0; k < 24; k++) xv[k] = in_s[lb + k];
    #pragma unroll 4
    for (int c = cb; c < cb + 32; c++) {
        float s1 = 0.f, s2 = 0.f;
        #pragma unroll
        for (int k = 0; k < 16; k++) {
            float wv = ws[c][k];
            s1 = fmaf(wv, xv[k], s1);
            s2 = fmaf(wv, xv[k + 8], s2);
        }
        float m = fmaxf(fmaxf(s1, s2) + bss[c], 0.f);
        g_y0[((size_t)b * 64 + c) * 624 + p] = scs[c] * m + shs[c];
    }
}

// ---------------- conv block 1 (16 pooled/CTA, 4oc x 4pos) ----------------
#define C1_IN   (64 * 132)
#define C1_WS   (4 * 8 * 128)
#define C1_SMEM ((C1_IN + C1_WS + 3 * 128) * 4)

__global__ __launch_bounds__(256) void conv1_kernel(
    const float* __restrict__ w, const float* __restrict__ bias,
    const float* __restrict__ bg, const float* __restrict__ bb,
    const float* __restrict__ bm, const float* __restrict__ bv) {
    extern __shared__ float c1s[];
    float* in_s = c1s;                       // [64][132]
    float* ws   = c1s + C1_IN;               // [4][8][128]
    float* scs  = ws + C1_WS;
    float* shs  = scs + 128;
    float* bss  = shs + 128;

    int b = blockIdx.y;
    int p0 = blockIdx.x * 16;
    int tid = threadIdx.x;
    int cg = tid & 31, pg = tid >> 5;

    for (int i = tid; i < C1_IN; i += 256) {
        int ic = i / 132, cc = i % 132;
        int col = 8 * p0 + cc;
        in_s[i] = (col < 624) ? g_y0[((size_t)b * 64 + ic) * 624 + col] : 0.f;
    }
    if (tid < 128) {
        float sc = bg[tid] * rsqrtf(bv[tid] + 1e-5f);
        scs[tid] = sc;
        shs[tid] = bb[tid] - bm[tid] * sc;
        bss[tid] = bias[tid];
    }
    float acc[4][4];
    #pragma unroll
    for (int i = 0; i < 4; i++)
        #pragma unroll
        for (int j = 0; j < 4; j++) acc[i][j] = 0.f;

    int ocl = tid & 127, half = tid >> 7;
    for (int ic0 = 0; ic0 < 64; ic0 += 4) {
        __syncthreads();
        #pragma unroll
        for (int il = 0; il < 2; il++) {
            int icl = half * 2 + il;
            const float4* src = (const float4*)(w + ((size_t)ocl * 64 + ic0 + icl) * 8);
            float4 v0 = src[0], v1 = src[1];
            float* wd = ws + icl * 1024 + ocl;
            wd[0 * 128] = v0.x; wd[1 * 128] = v0.y; wd[2 * 128] = v0.z; wd[3 * 128] = v0.w;
            wd[4 * 128] = v1.x; wd[5 * 128] = v1.y; wd[6 * 128] = v1.z; wd[7 * 128] = v1.w;
        }
        __syncthreads();
        #pragma unroll
        for (int icl = 0; icl < 4; icl++) {
            #pragma unroll
            for (int t = 0; t < 8; t++) {
                float4 w4 = *(const float4*)&ws[icl * 1024 + t * 128 + cg * 4];
                const float* ir = in_s + (ic0 + icl) * 132 + 16 * pg + t;
                #pragma unroll
                for (int qc = 0; qc < 4; qc++) {
                    float iv = ir[4 * qc];
                    acc[0][qc] = fmaf(w4.x, iv, acc[0][qc]);
                    acc[1][qc] = fmaf(w4.y, iv, acc[1][qc]);
                    acc[2][qc] = fmaf(w4.z, iv, acc[2][qc]);
                    acc[3][qc] = fmaf(w4.w, iv, acc[3][qc]);
                }
            }
        }
    }
    #pragma unroll
    for (int pp = 0; pp < 2; pp++) {
        int p = p0 + 2 * pg + pp;
        if (p >= 77) continue;
        float ov[4];
        #pragma unroll
        for (int i = 0; i < 4; i++) {
            int oc = 4 * cg + i;
            float m = fmaxf(acc[i][2 * pp], acc[i][2 * pp + 1]);
            float v = fmaxf(m + bss[oc], 0.f);
            ov[i] = scs[oc] * v + shs[oc];
        }
        *(float4*)&g_seq[((size_t)p * 256 + b) * 128 + 4 * cg] =
            make_float4(ov[0], ov[1], ov[2], ov[3]);
    }
}

// ---------------- input-projection GEMM (f32x2, double-buffered smem) ----------------
#define XP_BUF (16 * 132)
#define XP_SMEM (4 * XP_BUF * 4)

__global__ __launch_bounds__(256) void gemm_xproj_kernel(
    int src, const float* __restrict__ Wih,
    const float* __restrict__ b1, const float* __restrict__ b2) {
    extern __shared__ float xsm[];
    float* AsB = xsm;                 // [2][16][132]
    float* WsB = xsm + 2 * XP_BUF;    // [2][16][132]
    const int K = src ? 256 : 128;
    const float* A = src ? g_hs0 : g_seq;
    int n0 = blockIdx.x * 128, m0 = blockIdx.y * 128;
    int tid = threadIdx.x;
    int lr = tid >> 2, lq = tid & 3;
    int tx = tid & 15, ty = tid >> 4;
    unsigned long long acc2[8][4];
    #pragma unroll
    for (int i = 0; i < 8; i++)
        #pragma unroll
        for (int j = 0; j < 4; j++) acc2[i][j] = 0ull;

    const float* a0p = A + (size_t)(m0 + lr) * K + 4 * lq;
    const float* a1p = A + (size_t)(m0 + lr + 64) * K + 4 * lq;
    const float* w0p = Wih + (size_t)(n0 + lr) * K + 4 * lq;
    const float* w1p = Wih + (size_t)(n0 + lr + 64) * K + 4 * lq;

    float4 pa0 = *(const float4*)a0p;
    float4 pa1 = *(const float4*)a1p;
    float4 pw0 = *(const float4*)w0p;
    float4 pw1 = *(const float4*)w1p;

    int nch = K >> 4;
    for (int c = 0; c < nch; c++) {
        float* As = AsB + (c & 1) * XP_BUF;
        float* Ws = WsB + (c & 1) * XP_BUF;
        As[(4*lq+0)*132 + lr] = pa0.x; As[(4*lq+1)*132 + lr] = pa0.y;
        As[(4*lq+2)*132 + lr] = pa0.z; As[(4*lq+3)*132 + lr] = pa0.w;
        As[(4*lq+0)*132 + lr+64] = pa1.x; As[(4*lq+1)*132 + lr+64] = pa1.y;
        As[(4*lq+2)*132 + lr+64] = pa1.z; As[(4*lq+3)*132 + lr+64] = pa1.w;
        Ws[(4*lq+0)*132 + lr] = pw0.x; Ws[(4*lq+1)*132 + lr] = pw0.y;
        Ws[(4*lq+2)*132 + lr] = pw0.z; Ws[(4*lq+3)*132 + lr] = pw0.w;
        Ws[(4*lq+0)*132 + lr+64] = pw1.x; Ws[(4*lq+1)*132 + lr+64] = pw1.y;
        Ws[(4*lq+2)*132 + lr+64] = pw1.z; Ws[(4*lq+3)*132 + lr+64] = pw1.w;
        __syncthreads();
        if (c + 1 < nch) {
            int k0 = (c + 1) * 16;
            pa0 = *(const float4*)(a0p + k0);
            pa1 = *(const float4*)(a1p + k0);
            pw0 = *(const float4*)(w0p + k0);
            pw1 = *(const float4*)(w1p + k0);
        }
        #pragma unroll
        for (int kk = 0; kk < 16; kk++) {
            float a[8];
            *(float4*)&a[0] = *(const float4*)&As[kk*132 + 8 * ty];
            *(float4*)&a[4] = *(const float4*)&As[kk*132 + 8 * ty + 4];
            ulonglong2 bA = *(const ulonglong2*)&Ws[kk*132 + 8 * tx];
            ulonglong2 bB = *(const ulonglong2*)&Ws[kk*132 + 8 * tx + 4];
            #pragma unroll
            for (int i = 0; i < 8; i++) {
                unsigned long long ad = pk2(a[i], a[i]);
                fma2(acc2[i][0], ad, bA.x);
                fma2(acc2[i][1], ad, bA.y);
                fma2(acc2[i][2], ad, bB.x);
                fma2(acc2[i][3], ad, bB.y);
            }
        }
    }
    float bv[8];
    #pragma unroll
    for (int j = 0; j < 8; j++) {
        int n = n0 + 8 * tx + j;
        bv[j] = b1[n] + b2[n];
    }
    #pragma unroll
    for (int i = 0; i < 8; i++) {
        size_t row = (size_t)(m0 + 8 * ty + i) * 1024 + n0 + 8 * tx;
        float2 p0 = upk(acc2[i][0]), p1 = upk(acc2[i][1]);
        float2 p2 = upk(acc2[i][2]), p3 = upk(acc2[i][3]);
        float4 o0 = make_float4(p0.x + bv[0], p0.y + bv[1], p1.x + bv[2], p1.y + bv[3]);
        float4 o1 = make_float4(p2.x + bv[4], p2.y + bv[5], p3.x + bv[6], p3.y + bv[7]);
        *(float4*)&g_xp[row]     = o0;
        *(float4*)&g_xp[row + 4] = o1;
    }
}

// ---------------- persistent LSTM layer (v8.1: 512 threads, 1 CTA/SM pinned) ----------------
// Same as v8 but __launch_bounds__(512, 1): ptxas gets the full 128-reg budget,
// keeping the 32 u64 dup-packed weights register-resident (v8 spilled at 63 regs).
#define HSK 36
#define PS2_OFF (256 * HSK)
#define CS_OFF2 (PS2_OFF + 16 * 16 * 64 * 2)
#define LSTM_SMEM ((256 * HSK + 16 * 16 * 64 * 2 + 512) * 4)

__device__ __forceinline__ float sigf(float x) {
    return __fdividef(1.f, 1.f + __expf(-x));
}
__device__ __forceinline__ float tanhfast(float x) {
    return 2.f * sigf(2.f * x) - 1.f;
}

__global__ __launch_bounds__(512, 1) void lstm_persist_kernel(
    int layer, unsigned base, const float* __restrict__ Whh) {
    extern __shared__ float sm[];
    float* hs_s = sm;                 // [256][HSK] k-major h_prev tile
    float* ps2  = sm + PS2_OFF;       // [16][16][64][2] split-K partials
    float* c_s  = sm + CS_OFF2;       // [512] cell state

    int tid = threadIdx.x;
    int w = tid >> 5;                 // warp = k-slice (0..15)
    int lane = tid & 31;
    int bt = blockIdx.x >> 4, ht = blockIdx.x & 15;
    int b0 = bt * 32, h0 = ht * 16;
    float* hs = layer ? g_y0 : g_hs0;

    // ---- Whh slice, duplicate-packed (once per launch): k-slice of 16 ----
    unsigned long long wd0[16], wd1[16];
    {
        int gc0 = 2 * lane, gc1 = 2 * lane + 1;
        const float* r0 = Whh + (size_t)((gc0 >> 4) * 256 + h0 + (gc0 & 15)) * 256 + w * 16;
        const float* r1 = Whh + (size_t)((gc1 >> 4) * 256 + h0 + (gc1 & 15)) * 256 + w * 16;
        #pragma unroll
        for (int k = 0; k < 16; k++) {
            float w0 = r0[k], w1 = r1[k];
            wd0[k] = pk2(w0, w0);
            wd1[k] = pk2(w1, w1);
        }
    }
    c_s[tid] = 0.f;
    unsigned* cnt = &g_cnt[bt];

    int sb = tid & 31;                // stage: batch
    int skq = tid >> 5;               // stage: 16-k segment
    int ub = tid >> 4, uj = tid & 15; // pointwise unit (1 per thread)

    for (int t = 0; t < 77; t++) {
        // ---- prefetch xp for this step (independent of the barrier) ----
        const float* xp_t = g_xp + (size_t)t * 262144;
        const float* xr = xp_t + (size_t)(b0 + ub) * 1024 + h0 + uj;
        float xi = xr[0], xf = xr[256], xg = xr[512], xo = xr[768];

        // ---- wait for h(t-1) ----
        if (t > 0) {
            if (tid == 0) {
                unsigned target = base + 16u * (unsigned)t;
                while (*(volatile unsigned*)cnt < target) { }
                __threadfence();
            }
            __syncthreads();
        }

        // ---- stage h_prev into k-major tile (16 k per thread) ----
        if (t == 0) {
            #pragma unroll
            for (int i = 0; i < 16; i++)
                hs_s[(skq * 16 + i) * HSK + sb] = 0.f;
        } else {
            const float* srcp = hs + (size_t)(t - 1) * 65536 + (size_t)(b0 + sb) * 256 + skq * 16;
            #pragma unroll
            for (int i = 0; i < 16; i += 4) {
                float4 v = *(const float4*)&srcp[i];
                hs_s[(skq * 16 + i + 0) * HSK + sb] = v.x;
                hs_s[(skq * 16 + i + 1) * HSK + sb] = v.y;
                hs_s[(skq * 16 + i + 2) * HSK + sb] = v.z;
                hs_s[(skq * 16 + i + 3) * HSK + sb] = v.w;
            }
        }
        __syncthreads();

        // ---- split-K GEMM (f32x2): 8 groups of 4 batches, k-slice 16 ----
        {
            const float* apb = hs_s + (w * 16) * HSK;
            float* myps = ps2 + w * 2048;           // [16][64][2]
            int gc0 = 2 * lane, gc1 = 2 * lane + 1;
            #pragma unroll
            for (int grp = 0; grp < 8; grp++) {
                unsigned long long aA0 = 0ull, aA1 = 0ull, aB0 = 0ull, aB1 = 0ull;
                const float* ap = apb + grp * 4;
                #pragma unroll
                for (int k = 0; k < 16; k++) {
                    ulonglong2 av = *(const ulonglong2*)(ap + k * HSK);
                    fma2(aA0, av.x, wd0[k]);
                    fma2(aA1, av.y, wd0[k]);
                    fma2(aB0, av.x, wd1[k]);
                    fma2(aB1, av.y, wd1[k]);
                }
                int p0i = grp * 2, p1i = grp * 2 + 1;
                *(unsigned long long*)&myps[(p0i * 64 + gc0) * 2] = aA0;
                *(unsigned long long*)&myps[(p1i * 64 + gc0) * 2] = aA1;
                *(unsigned long long*)&myps[(p0i * 64 + gc1) * 2] = aB0;
                *(unsigned long long*)&myps[(p1i * 64 + gc1) * 2] = aB1;
            }
        }
        __syncthreads();

        // ---- pointwise: reduce 16 partials + prefetched xp; update c, write h ----
        {
            float* h_out = hs + (size_t)t * 65536;
            int b = ub, j = uj;
            int bp = (b >> 1), sel = (b & 1);
            float gi = xi, gf = xf, gg = xg, go = xo;
            #pragma unroll
            for (int qq = 0; qq < 16; qq++) {
                const float* p = ps2 + qq * 2048 + (bp * 64) * 2 + sel;
                gi += p[(j) * 2];
                gf += p[(16 + j) * 2];
                gg += p[(32 + j) * 2];
                go += p[(48 + j) * 2];
            }
            float c = sigf(gf) * c_s[tid] + sigf(gi) * tanhfast(gg);
            c_s[tid] = c;
            h_out[(size_t)(b0 + b) * 256 + h0 + j] = sigf(go) * tanhfast(c);
        }

        // ---- arrive (syncthreads orders block stores; tid0 fence publishes) ----
        if (t < 76) {
            __syncthreads();
            if (tid == 0) {
                __threadfence();
                atomicAdd(cnt, 1u);
            }
        }
    }
}

// ---------------- FC head ----------------
__global__ __launch_bounds__(256) void fc_kernel(
    int stage, const float* __restrict__ W, const float* __restrict__ bias,
    float* __restrict__ dout) {
    __shared__ float As[32][33];
    __shared__ float Ws[32][33];
    const float* A; float* out; int K, N; int relu;
    if (stage == 0) { A = g_y0 + (size_t)76 * 65536; out = g_f1; K = 256; N = 512; relu = 1; }
    else if (stage == 1) { A = g_f1; out = g_f2; K = 512; N = 512; relu = 1; }
    else { A = g_f2; out = dout; K = 512; N = 256; relu = 0; }
    int n0 = blockIdx.x * 32, m0 = blockIdx.y * 32;
    int tid = threadIdx.x;
    int lrow = tid >> 3, lkq = tid & 7;
    int ty = tid >> 4, tx = tid & 15;
    float acc[2][2] = {{0.f, 0.f}, {0.f, 0.f}};
    for (int k0 = 0; k0 < K; k0 += 32) {
        __syncthreads();
        {
            float4 va = *(const float4*)&A[(size_t)(m0 + lrow) * K + k0 + 4 * lkq];
            As[lrow][4*lkq+0] = va.x; As[lrow][4*lkq+1] = va.y;
            As[lrow][4*lkq+2] = va.z; As[lrow][4*lkq+3] = va.w;
            float4 vw = *(const float4*)&W[(size_t)(n0 + lrow) * K + k0 + 4 * lkq];
            Ws[lrow][4*lkq+0] = vw.x; Ws[lrow][4*lkq+1] = vw.y;
            Ws[lrow][4*lkq+2] = vw.z; Ws[lrow][4*lkq+3] = vw.w;
        }
        __syncthreads();
        #pragma unroll
        for (int kk = 0; kk < 32; kk++) {
            float a0 = As[2*ty][kk], a1 = As[2*ty+1][kk];
            float w0 = Ws[2*tx][kk], w1 = Ws[2*tx+1][kk];
            acc[0][0] = fmaf(a0, w0, acc[0][0]);
            acc[0][1] = fmaf(a0, w1, acc[0][1]);
            acc[1][0] = fmaf(a1, w0, acc[1][0]);
            acc[1][1] = fmaf(a1, w1, acc[1][1]);
        }
    }
    #pragma unroll
    for (int i = 0; i < 2; i++) {
        #pragma unroll
        for (int j = 0; j < 2; j++) {
            int m = m0 + 2 * ty + i, n = n0 + 2 * tx + j;
            float v = acc[i][j] + bias[n];
            if (relu) v = fmaxf(v, 0.f);
            out[(size_t)m * N + n] = v;
        }
    }
}

// ---------------- launch ----------------
extern "C" void kernel_launch(void* const* d_in, const int* in_sizes, int n_in,
                              void* d_out, int out_size) {
    const float* x       = (const float*)d_in[0];
    const float* conv_w0 = (const float*)d_in[1];
    const float* conv_b0 = (const float*)d_in[2];
    const float* bn_g0   = (const float*)d_in[3];
    const float* bn_b0   = (const float*)d_in[4];
    const float* bn_m0   = (const float*)d_in[5];
    const float* bn_v0   = (const float*)d_in[6];
    const float* conv_w1 = (const float*)d_in[7];
    const float* conv_b1 = (const float*)d_in[8];
    const float* bn_g1   = (const float*)d_in[9];
    const float* bn_b1   = (const float*)d_in[10];
    const float* bn_m1   = (const float*)d_in[11];
    const float* bn_v1   = (const float*)d_in[12];
    const float* Wih0    = (const float*)d_in[13];
    const float* Whh0    = (const float*)d_in[14];
    const float* bih0    = (const float*)d_in[15];
    const float* bhh0    = (const float*)d_in[16];
    const float* Wih1    = (const float*)d_in[17];
    const float* Whh1    = (const float*)d_in[18];
    const float* bih1    = (const float*)d_in[19];
    const float* bhh1    = (const float*)d_in[20];
    const float* fc0_w   = (const float*)d_in[21];
    const float* fc0_b   = (const float*)d_in[22];
    const float* fc1_w   = (const float*)d_in[23];
    const float* fc1_b   = (const float*)d_in[24];
    const float* out_w   = (const float*)d_in[25];
    const float* out_b   = (const float*)d_in[26];
    float* out = (float*)d_out;

    cudaFuncSetAttribute(lstm_persist_kernel,
                         cudaFuncAttributeMaxDynamicSharedMemorySize, LSTM_SMEM);
    cudaFuncSetAttribute(conv1_kernel,
                         cudaFuncAttributeMaxDynamicSharedMemorySize, C1_SMEM);
    cudaFuncSetAttribute(gemm_xproj_kernel,
                         cudaFuncAttributeMaxDynamicSharedMemorySize, XP_SMEM);

    conv0_kernel<<<dim3(5, 256), 256>>>(x, conv_w0, conv_b0, bn_g0, bn_b0, bn_m0, bn_v0);
    conv1_kernel<<<dim3(5, 256), 256, C1_SMEM>>>(conv_w1, conv_b1, bn_g1, bn_b1, bn_m1, bn_v1);

    gemm_xproj_kernel<<<dim3(8, 154), 256, XP_SMEM>>>(0, Wih0, bih0, bhh0);
    lstm_persist_kernel<<<128, 512, LSTM_SMEM>>>(0, 0u, Whh0);

    gemm_xproj_kernel<<<dim3(8, 154), 256, XP_SMEM>>>(1, Wih1, bih1, bhh1);
    lstm_persist_kernel<<<128, 512, LSTM_SMEM>>>(1, 16u * 76u, Whh1);

    fc_kernel<<<dim3(16, 8), 256>>>(0, fc0_w, fc0_b, out);
    fc_kernel<<<dim3(16, 8), 256>>>(1, fc1_w, fc1_b, out);
    fc_kernel<<<dim3(8, 8), 256>>>(2, out_w, out_b, out);
}

// round 15
// speedup vs baseline: 1.0081x; 1.0081x over previous
#include <cuda_runtime.h>
#include <math.h>

// ---------------- scratch (static __device__, allocation-free) ----------------
__device__ float g_y0 [256 * 64 * 624];     // conv block 0 out (b,c,p); reused as layer1 hs
__device__ float g_seq[77 * 256 * 128];     // conv block 1 out, (t,b,c)
__device__ float g_xp [77 * 256 * 1024];    // lstm input projection (t,b,4H), reused per layer
__device__ float g_hs0[77 * 256 * 256];     // layer0 hidden sequence (t,b,H)
__device__ float g_f1 [256 * 512];
__device__ float g_f2 [256 * 512];
__device__ unsigned g_cnt[8];               // per-batch-tile arrival counters

// SG(11,3) interior smoothing taps (symmetric): [-36,9,44,69,84,89,84,69,44,9,-36]/429
__constant__ float c_sg[11] = {
    -36.f/429.f, 9.f/429.f, 44.f/429.f, 69.f/429.f, 84.f/429.f, 89.f/429.f,
    84.f/429.f, 69.f/429.f, 44.f/429.f, 9.f/429.f, -36.f/429.f };

// ---------------- f32x2 packed-math helpers ----------------
__device__ __forceinline__ unsigned long long pk2(float a, float b) {
    unsigned long long r;
    asm("mov.b64 %0, {%1, %2};" : "=l"(r) : "f"(a), "f"(b));
    return r;
}
__device__ __forceinline__ void fma2(unsigned long long& d,
                                     unsigned long long a, unsigned long long b) {
    asm("fma.rn.f32x2 %0, %1, %2, %0;" : "+l"(d) : "l"(a), "l"(b));
}
__device__ __forceinline__ float2 upk(unsigned long long v) {
    float2 r;
    asm("mov.b64 {%0, %1}, %2;" : "=f"(r.x), "=f"(r.y) : "l"(v));
    return r;
}

// ---------------- savgol edge fit (cols 0..4 only; high edge is never consumed) ----------------
__device__ __forceinline__ void sg_fit(const float* __restrict__ xw, double a[4]) {
    double m0 = 0, m1 = 0, m2 = 0, m3 = 0;
    #pragma unroll
    for (int w = 0; w < 11; w++) {
        double y = (double)xw[w]; double t = (double)w;
        m0 += y; m1 += y * t; m2 += y * t * t; m3 += y * t * t * t;
    }
    double M[4][5] = {
        {11.0,    55.0,     385.0,     3025.0,    m0},
        {55.0,    385.0,    3025.0,    25333.0,   m1},
        {385.0,   3025.0,   25333.0,   220825.0,  m2},
        {3025.0,  25333.0,  220825.0,  1978405.0, m3}};
    #pragma unroll
    for (int i = 0; i < 4; i++) {
        double p = M[i][i];
        #pragma unroll
        for (int j = i; j < 5; j++) M[i][j] /= p;
        #pragma unroll
        for (int r = 0; r < 4; r++) {
            if (r != i) {
                double f = M[r][i];
                #pragma unroll
                for (int j = i; j < 5; j++) M[r][j] -= f * M[i][j];
            }
        }
    }
    a[0] = M[0][4]; a[1] = M[1][4]; a[2] = M[2][4]; a[3] = M[3][4];
}

// ---------------- conv block 0 (savgol fused; f32x2 over the two pooled conv positions) ----------------
__global__ __launch_bounds__(256) void conv0_kernel(
    const float* __restrict__ x,
    const float* __restrict__ w, const float* __restrict__ bias,
    const float* __restrict__ bg, const float* __restrict__ bb,
    const float* __restrict__ bm, const float* __restrict__ bv) {
    __shared__ float xs[2080];
    __shared__ float in_s[2064];
    __shared__ unsigned long long ws2[64][17];   // dup-packed (w,w); reads are warp-broadcast
    __shared__ float scs[64], shs[64], bss[64];
    int b = blockIdx.y;
    int p0 = blockIdx.x * 128;
    int tid = threadIdx.x;
    if (blockIdx.x == 0 && blockIdx.y == 0 && tid < 8) g_cnt[tid] = 0;
    int base = 16 * p0;
    const float* xr = x + (size_t)b * 10000;
    for (int i = tid; i < 2074; i += 256) {
        int col = base - 5 + i;
        xs[i] = (col >= 0 && col < 10000) ? xr[col] : 0.f;
    }
    for (int i = tid; i < 1024; i += 256) {
        float wv = w[i];
        ws2[i >> 4][i & 15] = pk2(wv, wv);
    }
    if (tid < 64) {
        float sc = bg[tid] * rsqrtf(bv[tid] + 1e-5f);
        scs[tid] = sc;
        shs[tid] = bb[tid] - bm[tid] * sc;
        bss[tid] = bias[tid];
    }
    __syncthreads();
    for (int i = tid; i < 2064; i += 256) {
        float acc = 0.f;
        #pragma unroll
        for (int j = 0; j < 11; j++) acc = fmaf(xs[i + j], c_sg[j], acc);
        in_s[i] = acc;
    }
    if (blockIdx.x == 0 && tid < 5) {
        double a[4]; sg_fit(xs + 5, a);
        double t = (double)tid;
        in_s[tid] = (float)(a[0] + t * (a[1] + t * (a[2] + t * a[3])));
    }
    __syncthreads();
    int p = p0 + (tid & 127);
    int cb = (tid >> 7) * 32;
    if (p >= 624) return;
    float xv[24];
    int lb = 16 * (tid & 127);
    #pragma unroll
    for (int k = 0; k < 24; k++) xv[k] = in_s[lb + k];
    unsigned long long px[16];
    #pragma unroll
    for (int k = 0; k < 16; k++) px[k] = pk2(xv[k], xv[k + 8]);
    #pragma unroll 4
    for (int c = cb; c < cb + 32; c++) {
        unsigned long long s2 = 0ull;
        #pragma unroll
        for (int k = 0; k < 16; k++) fma2(s2, px[k], ws2[c][k]);
        float2 s = upk(s2);
        float m = fmaxf(fmaxf(s.x, s.y) + bss[c], 0.f);
        g_y0[((size_t)b * 64 + c) * 624 + p] = scs[c] * m + shs[c];
    }
}

// ---------------- conv block 1 (16 pooled/CTA; f32x2 over oc pairs via register reinterpret) ----------------
#define C1_IN   (64 * 132)
#define C1_WS   (4 * 8 * 128)
#define C1_SMEM ((C1_IN + C1_WS + 3 * 128) * 4)

__global__ __launch_bounds__(256) void conv1_kernel(
    const float* __restrict__ w, const float* __restrict__ bias,
    const float* __restrict__ bg, const float* __restrict__ bb,
    const float* __restrict__ bm, const float* __restrict__ bv) {
    extern __shared__ float c1s[];
    float* in_s = c1s;                       // [64][132]
    float* ws   = c1s + C1_IN;               // [4][8][128] (plain floats, unchanged layout)
    float* scs  = ws + C1_WS;
    float* shs  = scs + 128;
    float* bss  = shs + 128;

    int b = blockIdx.y;
    int p0 = blockIdx.x * 16;
    int tid = threadIdx.x;
    int cg = tid & 31, pg = tid >> 5;

    for (int i = tid; i < C1_IN; i += 256) {
        int ic = i / 132, cc = i % 132;
        int col = 8 * p0 + cc;
        in_s[i] = (col < 624) ? g_y0[((size_t)b * 64 + ic) * 624 + col] : 0.f;
    }
    if (tid < 128) {
        float sc = bg[tid] * rsqrtf(bv[tid] + 1e-5f);
        scs[tid] = sc;
        shs[tid] = bb[tid] - bm[tid] * sc;
        bss[tid] = bias[tid];
    }
    unsigned long long acc2[2][4];   // [oc-pair][conv pos], pair=(4cg+2j, 4cg+2j+1)
    #pragma unroll
    for (int i = 0; i < 2; i++)
        #pragma unroll
        for (int j = 0; j < 4; j++) acc2[i][j] = 0ull;

    int ocl = tid & 127, half = tid >> 7;
    for (int ic0 = 0; ic0 < 64; ic0 += 4) {
        __syncthreads();
        #pragma unroll
        for (int il = 0; il < 2; il++) {
            int icl = half * 2 + il;
            const float4* src = (const float4*)(w + ((size_t)ocl * 64 + ic0 + icl) * 8);
            float4 v0 = src[0], v1 = src[1];
            float* wd = ws + icl * 1024 + ocl;
            wd[0 * 128] = v0.x; wd[1 * 128] = v0.y; wd[2 * 128] = v0.z; wd[3 * 128] = v0.w;
            wd[4 * 128] = v1.x; wd[5 * 128] = v1.y; wd[6 * 128] = v1.z; wd[7 * 128] = v1.w;
        }
        __syncthreads();
        #pragma unroll
        for (int icl = 0; icl < 4; icl++) {
            #pragma unroll
            for (int t = 0; t < 8; t++) {
                float4 w4 = *(const float4*)&ws[icl * 1024 + t * 128 + cg * 4];
                ulonglong2 wp = *(ulonglong2*)&w4;   // (w0,w1),(w2,w3) as f32x2 pairs
                const float* ir = in_s + (ic0 + icl) * 132 + 16 * pg + t;
                #pragma unroll
                for (int qc = 0; qc < 4; qc++) {
                    float iv = ir[4 * qc];
                    unsigned long long ivd = pk2(iv, iv);
                    fma2(acc2[0][qc], ivd, wp.x);
                    fma2(acc2[1][qc], ivd, wp.y);
                }
            }
        }
    }
    #pragma unroll
    for (int pp = 0; pp < 2; pp++) {
        int p = p0 + 2 * pg + pp;
        if (p >= 77) continue;
        float ov[4];
        #pragma unroll
        for (int j = 0; j < 2; j++) {
            float2 q0 = upk(acc2[j][2 * pp]);
            float2 q1 = upk(acc2[j][2 * pp + 1]);
            int oc0 = 4 * cg + 2 * j, oc1 = oc0 + 1;
            float m0 = fmaxf(q0.x, q1.x);
            float m1 = fmaxf(q0.y, q1.y);
            float v0 = fmaxf(m0 + bss[oc0], 0.f);
            float v1 = fmaxf(m1 + bss[oc1], 0.f);
            ov[2 * j]     = scs[oc0] * v0 + shs[oc0];
            ov[2 * j + 1] = scs[oc1] * v1 + shs[oc1];
        }
        *(float4*)&g_seq[((size_t)p * 256 + b) * 128 + 4 * cg] =
            make_float4(ov[0], ov[1], ov[2], ov[3]);
    }
}

// ---------------- input-projection GEMM (f32x2, double-buffered smem) ----------------
#define XP_BUF (16 * 132)
#define XP_SMEM (4 * XP_BUF * 4)

__global__ __launch_bounds__(256) void gemm_xproj_kernel(
    int src, const float* __restrict__ Wih,
    const float* __restrict__ b1, const float* __restrict__ b2) {
    extern __shared__ float xsm[];
    float* AsB = xsm;                 // [2][16][132]
    float* WsB = xsm + 2 * XP_BUF;    // [2][16][132]
    const int K = src ? 256 : 128;
    const float* A = src ? g_hs0 : g_seq;
    int n0 = blockIdx.x * 128, m0 = blockIdx.y * 128;
    int tid = threadIdx.x;
    int lr = tid >> 2, lq = tid & 3;
    int tx = tid & 15, ty = tid >> 4;
    unsigned long long acc2[8][4];
    #pragma unroll
    for (int i = 0; i < 8; i++)
        #pragma unroll
        for (int j = 0; j < 4; j++) acc2[i][j] = 0ull;

    const float* a0p = A + (size_t)(m0 + lr) * K + 4 * lq;
    const float* a1p = A + (size_t)(m0 + lr + 64) * K + 4 * lq;
    const float* w0p = Wih + (size_t)(n0 + lr) * K + 4 * lq;
    const float* w1p = Wih + (size_t)(n0 + lr + 64) * K + 4 * lq;

    float4 pa0 = *(const float4*)a0p;
    float4 pa1 = *(const float4*)a1p;
    float4 pw0 = *(const float4*)w0p;
    float4 pw1 = *(const float4*)w1p;

    int nch = K >> 4;
    for (int c = 0; c < nch; c++) {
        float* As = AsB + (c & 1) * XP_BUF;
        float* Ws = WsB + (c & 1) * XP_BUF;
        As[(4*lq+0)*132 + lr] = pa0.x; As[(4*lq+1)*132 + lr] = pa0.y;
        As[(4*lq+2)*132 + lr] = pa0.z; As[(4*lq+3)*132 + lr] = pa0.w;
        As[(4*lq+0)*132 + lr+64] = pa1.x; As[(4*lq+1)*132 + lr+64] = pa1.y;
        As[(4*lq+2)*132 + lr+64] = pa1.z; As[(4*lq+3)*132 + lr+64] = pa1.w;
        Ws[(4*lq+0)*132 + lr] = pw0.x; Ws[(4*lq+1)*132 + lr] = pw0.y;
        Ws[(4*lq+2)*132 + lr] = pw0.z; Ws[(4*lq+3)*132 + lr] = pw0.w;
        Ws[(4*lq+0)*132 + lr+64] = pw1.x; Ws[(4*lq+1)*132 + lr+64] = pw1.y;
        Ws[(4*lq+2)*132 + lr+64] = pw1.z; Ws[(4*lq+3)*132 + lr+64] = pw1.w;
        __syncthreads();
        if (c + 1 < nch) {
            int k0 = (c + 1) * 16;
            pa0 = *(const float4*)(a0p + k0);
            pa1 = *(const float4*)(a1p + k0);
            pw0 = *(const float4*)(w0p + k0);
            pw1 = *(const float4*)(w1p + k0);
        }
        #pragma unroll
        for (int kk = 0; kk < 16; kk++) {
            float a[8];
            *(float4*)&a[0] = *(const float4*)&As[kk*132 + 8 * ty];
            *(float4*)&a[4] = *(const float4*)&As[kk*132 + 8 * ty + 4];
            ulonglong2 bA = *(const ulonglong2*)&Ws[kk*132 + 8 * tx];
            ulonglong2 bB = *(const ulonglong2*)&Ws[kk*132 + 8 * tx + 4];
            #pragma unroll
            for (int i = 0; i < 8; i++) {
                unsigned long long ad = pk2(a[i], a[i]);
                fma2(acc2[i][0], ad, bA.x);
                fma2(acc2[i][1], ad, bA.y);
                fma2(acc2[i][2], ad, bB.x);
                fma2(acc2[i][3], ad, bB.y);
            }
        }
    }
    float bv[8];
    #pragma unroll
    for (int j = 0; j < 8; j++) {
        int n = n0 + 8 * tx + j;
        bv[j] = b1[n] + b2[n];
    }
    #pragma unroll
    for (int i = 0; i < 8; i++) {
        size_t row = (size_t)(m0 + 8 * ty + i) * 1024 + n0 + 8 * tx;
        float2 p0 = upk(acc2[i][0]), p1 = upk(acc2[i][1]);
        float2 p2 = upk(acc2[i][2]), p3 = upk(acc2[i][3]);
        float4 o0 = make_float4(p0.x + bv[0], p0.y + bv[1], p1.x + bv[2], p1.y + bv[3]);
        float4 o1 = make_float4(p2.x + bv[4], p2.y + bv[5], p3.x + bv[6], p3.y + bv[7]);
        *(float4*)&g_xp[row]     = o0;
        *(float4*)&g_xp[row + 4] = o1;
    }
}

// ---------------- persistent LSTM layer (v8: 512 threads, k-slice 16/warp) ----------------
#define HSK 36
#define PS2_OFF (256 * HSK)
#define CS_OFF2 (PS2_OFF + 16 * 16 * 64 * 2)
#define LSTM_SMEM ((256 * HSK + 16 * 16 * 64 * 2 + 512) * 4)

__device__ __forceinline__ float sigf(float x) {
    return __fdividef(1.f, 1.f + __expf(-x));
}
__device__ __forceinline__ float tanhfast(float x) {
    return 2.f * sigf(2.f * x) - 1.f;
}

__global__ __launch_bounds__(512) void lstm_persist_kernel(
    int layer, unsigned base, const float* __restrict__ Whh) {
    extern __shared__ float sm[];
    float* hs_s = sm;                 // [256][HSK] k-major h_prev tile
    float* ps2  = sm + PS2_OFF;       // [16][16][64][2] split-K partials
    float* c_s  = sm + CS_OFF2;       // [512] cell state

    int tid = threadIdx.x;
    int w = tid >> 5;                 // warp = k-slice (0..15)
    int lane = tid & 31;
    int bt = blockIdx.x >> 4, ht = blockIdx.x & 15;
    int b0 = bt * 32, h0 = ht * 16;
    float* hs = layer ? g_y0 : g_hs0;

    // ---- Whh slice, duplicate-packed (once per launch): k-slice of 16 ----
    unsigned long long wd0[16], wd1[16];
    {
        int gc0 = 2 * lane, gc1 = 2 * lane + 1;
        const float* r0 = Whh + (size_t)((gc0 >> 4) * 256 + h0 + (gc0 & 15)) * 256 + w * 16;
        const float* r1 = Whh + (size_t)((gc1 >> 4) * 256 + h0 + (gc1 & 15)) * 256 + w * 16;
        #pragma unroll
        for (int k = 0; k < 16; k++) {
            float w0 = r0[k], w1 = r1[k];
            wd0[k] = pk2(w0, w0);
            wd1[k] = pk2(w1, w1);
        }
    }
    c_s[tid] = 0.f;
    unsigned* cnt = &g_cnt[bt];

    int sb = tid & 31;                // stage: batch
    int skq = tid >> 5;               // stage: 16-k segment
    int ub = tid >> 4, uj = tid & 15; // pointwise unit (1 per thread)

    for (int t = 0; t < 77; t++) {
        // ---- prefetch xp for this step (independent of the barrier) ----
        const float* xp_t = g_xp + (size_t)t * 262144;
        const float* xr = xp_t + (size_t)(b0 + ub) * 1024 + h0 + uj;
        float xi = xr[0], xf = xr[256], xg = xr[512], xo = xr[768];

        // ---- wait for h(t-1) ----
        if (t > 0) {
            if (tid == 0) {
                unsigned target = base + 16u * (unsigned)t;
                while (*(volatile unsigned*)cnt < target) { }
                __threadfence();
            }
            __syncthreads();
        }

        // ---- stage h_prev into k-major tile (16 k per thread) ----
        if (t == 0) {
            #pragma unroll
            for (int i = 0; i < 16; i++)
                hs_s[(skq * 16 + i) * HSK + sb] = 0.f;
        } else {
            const float* srcp = hs + (size_t)(t - 1) * 65536 + (size_t)(b0 + sb) * 256 + skq * 16;
            #pragma unroll
            for (int i = 0; i < 16; i += 4) {
                float4 v = *(const float4*)&srcp[i];
                hs_s[(skq * 16 + i + 0) * HSK + sb] = v.x;
                hs_s[(skq * 16 + i + 1) * HSK + sb] = v.y;
                hs_s[(skq * 16 + i + 2) * HSK + sb] = v.z;
                hs_s[(skq * 16 + i + 3) * HSK + sb] = v.w;
            }
        }
        __syncthreads();

        // ---- split-K GEMM (f32x2): 8 groups of 4 batches, k-slice 16 ----
        {
            const float* apb = hs_s + (w * 16) * HSK;
            float* myps = ps2 + w * 2048;           // [16][64][2]
            int gc0 = 2 * lane, gc1 = 2 * lane + 1;
            #pragma unroll
            for (int grp = 0; grp < 8; grp++) {
                unsigned long long aA0 = 0ull, aA1 = 0ull, aB0 = 0ull, aB1 = 0ull;
                const float* ap = apb + grp * 4;
                #pragma unroll
                for (int k = 0; k < 16; k++) {
                    ulonglong2 av = *(const ulonglong2*)(ap + k * HSK);
                    fma2(aA0, av.x, wd0[k]);
                    fma2(aA1, av.y, wd0[k]);
                    fma2(aB0, av.x, wd1[k]);
                    fma2(aB1, av.y, wd1[k]);
                }
                int p0i = grp * 2, p1i = grp * 2 + 1;
                *(unsigned long long*)&myps[(p0i * 64 + gc0) * 2] = aA0;
                *(unsigned long long*)&myps[(p1i * 64 + gc0) * 2] = aA1;
                *(unsigned long long*)&myps[(p0i * 64 + gc1) * 2] = aB0;
                *(unsigned long long*)&myps[(p1i * 64 + gc1) * 2] = aB1;
            }
        }
        __syncthreads();

        // ---- pointwise: reduce 16 partials + prefetched xp; update c, write h ----
        {
            float* h_out = hs + (size_t)t * 65536;
            int b = ub, j = uj;
            int bp = (b >> 1), sel = (b & 1);
            float gi = xi, gf = xf, gg = xg, go = xo;
            #pragma unroll
            for (int qq = 0; qq < 16; qq++) {
                const float* p = ps2 + qq * 2048 + (bp * 64) * 2 + sel;
                gi += p[(j) * 2];
                gf += p[(16 + j) * 2];
                gg += p[(32 + j) * 2];
                go += p[(48 + j) * 2];
            }
            float c = sigf(gf) * c_s[tid] + sigf(gi) * tanhfast(gg);
            c_s[tid] = c;
            h_out[(size_t)(b0 + b) * 256 + h0 + j] = sigf(go) * tanhfast(c);
        }

        // ---- arrive (syncthreads orders block stores; tid0 fence publishes) ----
        if (t < 76) {
            __syncthreads();
            if (tid == 0) {
                __threadfence();
                atomicAdd(cnt, 1u);
            }
        }
    }
}

// ---------------- FC head ----------------
__global__ __launch_bounds__(256) void fc_kernel(
    int stage, const float* __restrict__ W, const float* __restrict__ bias,
    float* __restrict__ dout) {
    __shared__ float As[32][33];
    __shared__ float Ws[32][33];
    const float* A; float* out; int K, N; int relu;
    if (stage == 0) { A = g_y0 + (size_t)76 * 65536; out = g_f1; K = 256; N = 512; relu = 1; }
    else if (stage == 1) { A = g_f1; out = g_f2; K = 512; N = 512; relu = 1; }
    else { A = g_f2; out = dout; K = 512; N = 256; relu = 0; }
    int n0 = blockIdx.x * 32, m0 = blockIdx.y * 32;
    int tid = threadIdx.x;
    int lrow = tid >> 3, lkq = tid & 7;
    int ty = tid >> 4, tx = tid & 15;
    float acc[2][2] = {{0.f, 0.f}, {0.f, 0.f}};
    for (int k0 = 0; k0 < K; k0 += 32) {
        __syncthreads();
        {
            float4 va = *(const float4*)&A[(size_t)(m0 + lrow) * K + k0 + 4 * lkq];
            As[lrow][4*lkq+0] = va.x; As[lrow][4*lkq+1] = va.y;
            As[lrow][4*lkq+2] = va.z; As[lrow][4*lkq+3] = va.w;
            float4 vw = *(const float4*)&W[(size_t)(n0 + lrow) * K + k0 + 4 * lkq];
            Ws[lrow][4*lkq+0] = vw.x; Ws[lrow][4*lkq+1] = vw.y;
            Ws[lrow][4*lkq+2] = vw.z; Ws[lrow][4*lkq+3] = vw.w;
        }
        __syncthreads();
        #pragma unroll
        for (int kk = 0; kk < 32; kk++) {
            float a0 = As[2*ty][kk], a1 = As[2*ty+1][kk];
            float w0 = Ws[2*tx][kk], w1 = Ws[2*tx+1][kk];
            acc[0][0] = fmaf(a0, w0, acc[0][0]);
            acc[0][1] = fmaf(a0, w1, acc[0][1]);
            acc[1][0] = fmaf(a1, w0, acc[1][0]);
            acc[1][1] = fmaf(a1, w1, acc[1][1]);
        }
    }
    #pragma unroll
    for (int i = 0; i < 2; i++) {
        #pragma unroll
        for (int j = 0; j < 2; j++) {
            int m = m0 + 2 * ty + i, n = n0 + 2 * tx + j;
            float v = acc[i][j] + bias[n];
            if (relu) v = fmaxf(v, 0.f);
            out[(size_t)m * N + n] = v;
        }
    }
}

// ---------------- launch ----------------
extern "C" void kernel_launch(void* const* d_in, const int* in_sizes, int n_in,
                              void* d_out, int out_size) {
    const float* x       = (const float*)d_in[0];
    const float* conv_w0 = (const float*)d_in[1];
    const float* conv_b0 = (const float*)d_in[2];
    const float* bn_g0   = (const float*)d_in[3];
    const float* bn_b0   = (const float*)d_in[4];
    const float* bn_m0   = (const float*)d_in[5];
    const float* bn_v0   = (const float*)d_in[6];
    const float* conv_w1 = (const float*)d_in[7];
    const float* conv_b1 = (const float*)d_in[8];
    const float* bn_g1   = (const float*)d_in[9];
    const float* bn_b1   = (const float*)d_in[10];
    const float* bn_m1   = (const float*)d_in[11];
    const float* bn_v1   = (const float*)d_in[12];
    const float* Wih0    = (const float*)d_in[13];
    const float* Whh0    = (const float*)d_in[14];
    const float* bih0    = (const float*)d_in[15];
    const float* bhh0    = (const float*)d_in[16];
    const float* Wih1    = (const float*)d_in[17];
    const float* Whh1    = (const float*)d_in[18];
    const float* bih1    = (const float*)d_in[19];
    const float* bhh1    = (const float*)d_in[20];
    const float* fc0_w   = (const float*)d_in[21];
    const float* fc0_b   = (const float*)d_in[22];
    const float* fc1_w   = (const float*)d_in[23];
    const float* fc1_b   = (const float*)d_in[24];
    const float* out_w   = (const float*)d_in[25];
    const float* out_b   = (const float*)d_in[26];
    float* out = (float*)d_out;

    cudaFuncSetAttribute(lstm_persist_kernel,
                         cudaFuncAttributeMaxDynamicSharedMemorySize, LSTM_SMEM);
    cudaFuncSetAttribute(conv1_kernel,
                         cudaFuncAttributeMaxDynamicSharedMemorySize, C1_SMEM);
    cudaFuncSetAttribute(gemm_xproj_kernel,
                         cudaFuncAttributeMaxDynamicSharedMemorySize, XP_SMEM);

    conv0_kernel<<<dim3(5, 256), 256>>>(x, conv_w0, conv_b0, bn_g0, bn_b0, bn_m0, bn_v0);
    conv1_kernel<<<dim3(5, 256), 256, C1_SMEM>>>(conv_w1, conv_b1, bn_g1, bn_b1, bn_m1, bn_v1);

    gemm_xproj_kernel<<<dim3(8, 154), 256, XP_SMEM>>>(0, Wih0, bih0, bhh0);
    lstm_persist_kernel<<<128, 512, LSTM_SMEM>>>(0, 0u, Whh0);

    gemm_xproj_kernel<<<dim3(8, 154), 256, XP_SMEM>>>(1, Wih1, bih1, bhh1);
    lstm_persist_kernel<<<128, 512, LSTM_SMEM>>>(1, 16u * 76u, Whh1);

    fc_kernel<<<dim3(16, 8), 256>>>(0, fc0_w, fc0_b, out);
    fc_kernel<<<dim3(16, 8), 256>>>(1, fc1_w, fc1_b, out);
    fc_kernel<<<dim3(8, 8), 256>>>(2, out_w, out_b, out);
}

// round 16
// speedup vs baseline: 1.0628x; 1.0542x over previous
#include <cuda_runtime.h>
#include <math.h>

// ---------------- scratch (static __device__, allocation-free) ----------------
__device__ float g_y0 [256 * 64 * 624];     // conv block 0 out (b,c,p); reused as layer1 hs
__device__ float g_seq[77 * 256 * 128];     // conv block 1 out, (t,b,c)
__device__ float g_xp [77 * 256 * 1024];    // lstm input projection (t,b,4H), reused per layer
__device__ float g_hs0[77 * 256 * 256];     // layer0 hidden sequence (t,b,H)
__device__ float g_hT [77 * 256 * 256];     // hidden sequence, k-major (t,k,b) - recurrent reads
__device__ float g_f1 [256 * 512];
__device__ float g_f2 [256 * 512];
__device__ unsigned g_cnt[8];               // per-batch-tile arrival counters

// SG(11,3) interior smoothing taps (symmetric): [-36,9,44,69,84,89,84,69,44,9,-36]/429
__constant__ float c_sg[11] = {
    -36.f/429.f, 9.f/429.f, 44.f/429.f, 69.f/429.f, 84.f/429.f, 89.f/429.f,
    84.f/429.f, 69.f/429.f, 44.f/429.f, 9.f/429.f, -36.f/429.f };

// ---------------- f32x2 packed-math helpers ----------------
__device__ __forceinline__ unsigned long long pk2(float a, float b) {
    unsigned long long r;
    asm("mov.b64 %0, {%1, %2};" : "=l"(r) : "f"(a), "f"(b));
    return r;
}
__device__ __forceinline__ void fma2(unsigned long long& d,
                                     unsigned long long a, unsigned long long b) {
    asm("fma.rn.f32x2 %0, %1, %2, %0;" : "+l"(d) : "l"(a), "l"(b));
}
__device__ __forceinline__ float2 upk(unsigned long long v) {
    float2 r;
    asm("mov.b64 {%0, %1}, %2;" : "=f"(r.x), "=f"(r.y) : "l"(v));
    return r;
}

// ---------------- savgol edge fit (cols 0..4 only; high edge is never consumed) ----------------
__device__ __forceinline__ void sg_fit(const float* __restrict__ xw, double a[4]) {
    double m0 = 0, m1 = 0, m2 = 0, m3 = 0;
    #pragma unroll
    for (int w = 0; w < 11; w++) {
        double y = (double)xw[w]; double t = (double)w;
        m0 += y; m1 += y * t; m2 += y * t * t; m3 += y * t * t * t;
    }
    double M[4][5] = {
        {11.0,    55.0,     385.0,     3025.0,    m0},
        {55.0,    385.0,    3025.0,    25333.0,   m1},
        {385.0,   3025.0,   25333.0,   220825.0,  m2},
        {3025.0,  25333.0,  220825.0,  1978405.0, m3}};
    #pragma unroll
    for (int i = 0; i < 4; i++) {
        double p = M[i][i];
        #pragma unroll
        for (int j = i; j < 5; j++) M[i][j] /= p;
        #pragma unroll
        for (int r = 0; r < 4; r++) {
            if (r != i) {
                double f = M[r][i];
                #pragma unroll
                for (int j = i; j < 5; j++) M[r][j] -= f * M[i][j];
            }
        }
    }
    a[0] = M[0][4]; a[1] = M[1][4]; a[2] = M[2][4]; a[3] = M[3][4];
}

// ---------------- conv block 0 (savgol fused; f32x2 over the two pooled conv positions) ----------------
__global__ __launch_bounds__(256) void conv0_kernel(
    const float* __restrict__ x,
    const float* __restrict__ w, const float* __restrict__ bias,
    const float* __restrict__ bg, const float* __restrict__ bb,
    const float* __restrict__ bm, const float* __restrict__ bv) {
    __shared__ float xs[2080];
    __shared__ float in_s[2064];
    __shared__ unsigned long long ws2[64][17];   // dup-packed (w,w); reads are warp-broadcast
    __shared__ float scs[64], shs[64], bss[64];
    int b = blockIdx.y;
    int p0 = blockIdx.x * 128;
    int tid = threadIdx.x;
    if (blockIdx.x == 0 && blockIdx.y == 0 && tid < 8) g_cnt[tid] = 0;
    int base = 16 * p0;
    const float* xr = x + (size_t)b * 10000;
    for (int i = tid; i < 2074; i += 256) {
        int col = base - 5 + i;
        xs[i] = (col >= 0 && col < 10000) ? xr[col] : 0.f;
    }
    for (int i = tid; i < 1024; i += 256) {
        float wv = w[i];
        ws2[i >> 4][i & 15] = pk2(wv, wv);
    }
    if (tid < 64) {
        float sc = bg[tid] * rsqrtf(bv[tid] + 1e-5f);
        scs[tid] = sc;
        shs[tid] = bb[tid] - bm[tid] * sc;
        bss[tid] = bias[tid];
    }
    __syncthreads();
    for (int i = tid; i < 2064; i += 256) {
        float acc = 0.f;
        #pragma unroll
        for (int j = 0; j < 11; j++) acc = fmaf(xs[i + j], c_sg[j], acc);
        in_s[i] = acc;
    }
    if (blockIdx.x == 0 && tid < 5) {
        double a[4]; sg_fit(xs + 5, a);
        double t = (double)tid;
        in_s[tid] = (float)(a[0] + t * (a[1] + t * (a[2] + t * a[3])));
    }
    __syncthreads();
    int p = p0 + (tid & 127);
    int cb = (tid >> 7) * 32;
    if (p >= 624) return;
    float xv[24];
    int lb = 16 * (tid & 127);
    #pragma unroll
    for (int k = 0; k < 24; k++) xv[k] = in_s[lb + k];
    unsigned long long px[16];
    #pragma unroll
    for (int k = 0; k < 16; k++) px[k] = pk2(xv[k], xv[k + 8]);
    #pragma unroll 4
    for (int c = cb; c < cb + 32; c++) {
        unsigned long long s2 = 0ull;
        #pragma unroll
        for (int k = 0; k < 16; k++) fma2(s2, px[k], ws2[c][k]);
        float2 s = upk(s2);
        float m = fmaxf(fmaxf(s.x, s.y) + bss[c], 0.f);
        g_y0[((size_t)b * 64 + c) * 624 + p] = scs[c] * m + shs[c];
    }
}

// ---------------- conv block 1 (16 pooled/CTA; f32x2 over oc pairs via register reinterpret) ----------------
#define C1_IN   (64 * 132)
#define C1_WS   (4 * 8 * 128)
#define C1_SMEM ((C1_IN + C1_WS + 3 * 128) * 4)

__global__ __launch_bounds__(256) void conv1_kernel(
    const float* __restrict__ w, const float* __restrict__ bias,
    const float* __restrict__ bg, const float* __restrict__ bb,
    const float* __restrict__ bm, const float* __restrict__ bv) {
    extern __shared__ float c1s[];
    float* in_s = c1s;                       // [64][132]
    float* ws   = c1s + C1_IN;               // [4][8][128]
    float* scs  = ws + C1_WS;
    float* shs  = scs + 128;
    float* bss  = shs + 128;

    int b = blockIdx.y;
    int p0 = blockIdx.x * 16;
    int tid = threadIdx.x;
    int cg = tid & 31, pg = tid >> 5;

    for (int i = tid; i < C1_IN; i += 256) {
        int ic = i / 132, cc = i % 132;
        int col = 8 * p0 + cc;
        in_s[i] = (col < 624) ? g_y0[((size_t)b * 64 + ic) * 624 + col] : 0.f;
    }
    if (tid < 128) {
        float sc = bg[tid] * rsqrtf(bv[tid] + 1e-5f);
        scs[tid] = sc;
        shs[tid] = bb[tid] - bm[tid] * sc;
        bss[tid] = bias[tid];
    }
    unsigned long long acc2[2][4];   // [oc-pair][conv pos], pair=(4cg+2j, 4cg+2j+1)
    #pragma unroll
    for (int i = 0; i < 2; i++)
        #pragma unroll
        for (int j = 0; j < 4; j++) acc2[i][j] = 0ull;

    int ocl = tid & 127, half = tid >> 7;
    for (int ic0 = 0; ic0 < 64; ic0 += 4) {
        __syncthreads();
        #pragma unroll
        for (int il = 0; il < 2; il++) {
            int icl = half * 2 + il;
            const float4* src = (const float4*)(w + ((size_t)ocl * 64 + ic0 + icl) * 8);
            float4 v0 = src[0], v1 = src[1];
            float* wd = ws + icl * 1024 + ocl;
            wd[0 * 128] = v0.x; wd[1 * 128] = v0.y; wd[2 * 128] = v0.z; wd[3 * 128] = v0.w;
            wd[4 * 128] = v1.x; wd[5 * 128] = v1.y; wd[6 * 128] = v1.z; wd[7 * 128] = v1.w;
        }
        __syncthreads();
        #pragma unroll
        for (int icl = 0; icl < 4; icl++) {
            #pragma unroll
            for (int t = 0; t < 8; t++) {
                float4 w4 = *(const float4*)&ws[icl * 1024 + t * 128 + cg * 4];
                ulonglong2 wp = *(ulonglong2*)&w4;   // (w0,w1),(w2,w3) as f32x2 pairs
                const float* ir = in_s + (ic0 + icl) * 132 + 16 * pg + t;
                #pragma unroll
                for (int qc = 0; qc < 4; qc++) {
                    float iv = ir[4 * qc];
                    unsigned long long ivd = pk2(iv, iv);
                    fma2(acc2[0][qc], ivd, wp.x);
                    fma2(acc2[1][qc], ivd, wp.y);
                }
            }
        }
    }
    #pragma unroll
    for (int pp = 0; pp < 2; pp++) {
        int p = p0 + 2 * pg + pp;
        if (p >= 77) continue;
        float ov[4];
        #pragma unroll
        for (int j = 0; j < 2; j++) {
            float2 q0 = upk(acc2[j][2 * pp]);
            float2 q1 = upk(acc2[j][2 * pp + 1]);
            int oc0 = 4 * cg + 2 * j, oc1 = oc0 + 1;
            float m0 = fmaxf(q0.x, q1.x);
            float m1 = fmaxf(q0.y, q1.y);
            float v0 = fmaxf(m0 + bss[oc0], 0.f);
            float v1 = fmaxf(m1 + bss[oc1], 0.f);
            ov[2 * j]     = scs[oc0] * v0 + shs[oc0];
            ov[2 * j + 1] = scs[oc1] * v1 + shs[oc1];
        }
        *(float4*)&g_seq[((size_t)p * 256 + b) * 128 + 4 * cg] =
            make_float4(ov[0], ov[1], ov[2], ov[3]);
    }
}

// ---------------- input-projection GEMM (f32x2, double-buffered smem) ----------------
#define XP_BUF (16 * 132)
#define XP_SMEM (4 * XP_BUF * 4)

__global__ __launch_bounds__(256) void gemm_xproj_kernel(
    int src, const float* __restrict__ Wih,
    const float* __restrict__ b1, const float* __restrict__ b2) {
    extern __shared__ float xsm[];
    float* AsB = xsm;                 // [2][16][132]
    float* WsB = xsm + 2 * XP_BUF;    // [2][16][132]
    const int K = src ? 256 : 128;
    const float* A = src ? g_hs0 : g_seq;
    int n0 = blockIdx.x * 128, m0 = blockIdx.y * 128;
    int tid = threadIdx.x;
    int lr = tid >> 2, lq = tid & 3;
    int tx = tid & 15, ty = tid >> 4;
    unsigned long long acc2[8][4];
    #pragma unroll
    for (int i = 0; i < 8; i++)
        #pragma unroll
        for (int j = 0; j < 4; j++) acc2[i][j] = 0ull;

    const float* a0p = A + (size_t)(m0 + lr) * K + 4 * lq;
    const float* a1p = A + (size_t)(m0 + lr + 64) * K + 4 * lq;
    const float* w0p = Wih + (size_t)(n0 + lr) * K + 4 * lq;
    const float* w1p = Wih + (size_t)(n0 + lr + 64) * K + 4 * lq;

    float4 pa0 = *(const float4*)a0p;
    float4 pa1 = *(const float4*)a1p;
    float4 pw0 = *(const float4*)w0p;
    float4 pw1 = *(const float4*)w1p;

    int nch = K >> 4;
    for (int c = 0; c < nch; c++) {
        float* As = AsB + (c & 1) * XP_BUF;
        float* Ws = WsB + (c & 1) * XP_BUF;
        As[(4*lq+0)*132 + lr] = pa0.x; As[(4*lq+1)*132 + lr] = pa0.y;
        As[(4*lq+2)*132 + lr] = pa0.z; As[(4*lq+3)*132 + lr] = pa0.w;
        As[(4*lq+0)*132 + lr+64] = pa1.x; As[(4*lq+1)*132 + lr+64] = pa1.y;
        As[(4*lq+2)*132 + lr+64] = pa1.z; As[(4*lq+3)*132 + lr+64] = pa1.w;
        Ws[(4*lq+0)*132 + lr] = pw0.x; Ws[(4*lq+1)*132 + lr] = pw0.y;
        Ws[(4*lq+2)*132 + lr] = pw0.z; Ws[(4*lq+3)*132 + lr] = pw0.w;
        Ws[(4*lq+0)*132 + lr+64] = pw1.x; Ws[(4*lq+1)*132 + lr+64] = pw1.y;
        Ws[(4*lq+2)*132 + lr+64] = pw1.z; Ws[(4*lq+3)*132 + lr+64] = pw1.w;
        __syncthreads();
        if (c + 1 < nch) {
            int k0 = (c + 1) * 16;
            pa0 = *(const float4*)(a0p + k0);
            pa1 = *(const float4*)(a1p + k0);
            pw0 = *(const float4*)(w0p + k0);
            pw1 = *(const float4*)(w1p + k0);
        }
        #pragma unroll
        for (int kk = 0; kk < 16; kk++) {
            float a[8];
            *(float4*)&a[0] = *(const float4*)&As[kk*132 + 8 * ty];
            *(float4*)&a[4] = *(const float4*)&As[kk*132 + 8 * ty + 4];
            ulonglong2 bA = *(const ulonglong2*)&Ws[kk*132 + 8 * tx];
            ulonglong2 bB = *(const ulonglong2*)&Ws[kk*132 + 8 * tx + 4];
            #pragma unroll
            for (int i = 0; i < 8; i++) {
                unsigned long long ad = pk2(a[i], a[i]);
                fma2(acc2[i][0], ad, bA.x);
                fma2(acc2[i][1], ad, bA.y);
                fma2(acc2[i][2], ad, bB.x);
                fma2(acc2[i][3], ad, bB.y);
            }
        }
    }
    float bv[8];
    #pragma unroll
    for (int j = 0; j < 8; j++) {
        int n = n0 + 8 * tx + j;
        bv[j] = b1[n] + b2[n];
    }
    #pragma unroll
    for (int i = 0; i < 8; i++) {
        size_t row = (size_t)(m0 + 8 * ty + i) * 1024 + n0 + 8 * tx;
        float2 p0 = upk(acc2[i][0]), p1 = upk(acc2[i][1]);
        float2 p2 = upk(acc2[i][2]), p3 = upk(acc2[i][3]);
        float4 o0 = make_float4(p0.x + bv[0], p0.y + bv[1], p1.x + bv[2], p1.y + bv[3]);
        float4 o1 = make_float4(p2.x + bv[4], p2.y + bv[5], p3.x + bv[6], p3.y + bv[7]);
        *(float4*)&g_xp[row]     = o0;
        *(float4*)&g_xp[row + 4] = o1;
    }
}

// ---------------- persistent LSTM layer (v9: k-major hT stream, coalesced staging) ----------------
// 128 CTAs (8 bt x 16 ht) x 512 threads. CTA tile: 32 batch x 64 gatecols.
// Warp w = k-slice [16w,+16); lane owns gatecols {2lane, 2lane+1} (dup-packed regs).
// h written twice: b-major sequence (xproj/fc) + k-major g_hT (recurrent reads).
// Staging = straight coalesced copy of the hT tile (no transpose).
#define PS2_OFF (256 * 32)
#define CS_OFF2 (PS2_OFF + 16 * 16 * 64 * 2)
#define LSTM_SMEM ((256 * 32 + 16 * 16 * 64 * 2 + 512) * 4)

__device__ __forceinline__ float sigf(float x) {
    return __fdividef(1.f, 1.f + __expf(-x));
}
__device__ __forceinline__ float tanhfast(float x) {
    return 2.f * sigf(2.f * x) - 1.f;
}

__global__ __launch_bounds__(512) void lstm_persist_kernel(
    int layer, unsigned base, const float* __restrict__ Whh) {
    extern __shared__ float sm[];
    float* hs_s = sm;                 // [256][32] k-major h_prev tile (no padding)
    float* ps2  = sm + PS2_OFF;       // [16][16][64][2] split-K partials
    float* c_s  = sm + CS_OFF2;       // [512] cell state

    int tid = threadIdx.x;
    int w = tid >> 5;                 // warp = k-slice (0..15)
    int lane = tid & 31;
    int bt = blockIdx.x >> 4, ht = blockIdx.x & 15;
    int b0 = bt * 32, h0 = ht * 16;
    float* hs = layer ? g_y0 : g_hs0;

    // ---- Whh slice, duplicate-packed (once per launch): k-slice of 16 ----
    unsigned long long wd0[16], wd1[16];
    {
        int gc0 = 2 * lane, gc1 = 2 * lane + 1;
        const float* r0 = Whh + (size_t)((gc0 >> 4) * 256 + h0 + (gc0 & 15)) * 256 + w * 16;
        const float* r1 = Whh + (size_t)((gc1 >> 4) * 256 + h0 + (gc1 & 15)) * 256 + w * 16;
        #pragma unroll
        for (int k = 0; k < 16; k++) {
            float w0 = r0[k], w1 = r1[k];
            wd0[k] = pk2(w0, w0);
            wd1[k] = pk2(w1, w1);
        }
    }
    c_s[tid] = 0.f;
    unsigned* cnt = &g_cnt[bt];

    int ub = tid >> 4, uj = tid & 15; // pointwise unit (1 per thread)

    for (int t = 0; t < 77; t++) {
        // ---- prefetch xp for this step (independent of the barrier) ----
        const float* xp_t = g_xp + (size_t)t * 262144;
        const float* xr = xp_t + (size_t)(b0 + ub) * 1024 + h0 + uj;
        float xi = xr[0], xf = xr[256], xg = xr[512], xo = xr[768];

        // ---- wait for h(t-1) ----
        if (t > 0) {
            if (tid == 0) {
                unsigned target = base + 16u * (unsigned)t;
                while (*(volatile unsigned*)cnt < target) { }
                __threadfence();
            }
            __syncthreads();
        }

        // ---- stage: coalesced copy of hT tile (256 k x 32 b) ----
        if (t == 0) {
            float4 z = make_float4(0.f, 0.f, 0.f, 0.f);
            #pragma unroll
            for (int it = 0; it < 4; it++)
                ((float4*)hs_s)[tid + 512 * it] = z;
        } else {
            const float* src = g_hT + (size_t)(t - 1) * 65536 + b0;
            #pragma unroll
            for (int it = 0; it < 4; it++) {
                int lin = tid + 512 * it;
                int k = lin >> 3, cc = lin & 7;
                ((float4*)hs_s)[lin] = *(const float4*)(src + k * 256 + 4 * cc);
            }
        }
        __syncthreads();

        // ---- split-K GEMM (f32x2): 8 groups of 4 batches, k-slice 16 ----
        {
            const float* apb = hs_s + (w * 16) * 32;
            float* myps = ps2 + w * 2048;           // [16][64][2]
            int gc0 = 2 * lane, gc1 = 2 * lane + 1;
            #pragma unroll
            for (int grp = 0; grp < 8; grp++) {
                unsigned long long aA0 = 0ull, aA1 = 0ull, aB0 = 0ull, aB1 = 0ull;
                const float* ap = apb + grp * 4;
                #pragma unroll
                for (int k = 0; k < 16; k++) {
                    ulonglong2 av = *(const ulonglong2*)(ap + k * 32);
                    fma2(aA0, av.x, wd0[k]);
                    fma2(aA1, av.y, wd0[k]);
                    fma2(aB0, av.x, wd1[k]);
                    fma2(aB1, av.y, wd1[k]);
                }
                int p0i = grp * 2, p1i = grp * 2 + 1;
                *(unsigned long long*)&myps[(p0i * 64 + gc0) * 2] = aA0;
                *(unsigned long long*)&myps[(p1i * 64 + gc0) * 2] = aA1;
                *(unsigned long long*)&myps[(p0i * 64 + gc1) * 2] = aB0;
                *(unsigned long long*)&myps[(p1i * 64 + gc1) * 2] = aB1;
            }
        }
        __syncthreads();

        // ---- pointwise: reduce 16 partials + prefetched xp; update c, write h (x2) ----
        {
            float* h_out = hs + (size_t)t * 65536;
            int b = ub, j = uj;
            int bp = (b >> 1), sel = (b & 1);
            float gi = xi, gf = xf, gg = xg, go = xo;
            #pragma unroll
            for (int qq = 0; qq < 16; qq++) {
                const float* p = ps2 + qq * 2048 + (bp * 64) * 2 + sel;
                gi += p[(j) * 2];
                gf += p[(16 + j) * 2];
                gg += p[(32 + j) * 2];
                go += p[(48 + j) * 2];
            }
            float c = sigf(gf) * c_s[tid] + sigf(gi) * tanhfast(gg);
            c_s[tid] = c;
            float hv = sigf(go) * tanhfast(c);
            h_out[(size_t)(b0 + b) * 256 + h0 + j] = hv;
            g_hT[(size_t)t * 65536 + (size_t)(h0 + j) * 256 + b0 + b] = hv;
        }

        // ---- arrive (syncthreads orders block stores; tid0 fence publishes) ----
        if (t < 76) {
            __syncthreads();
            if (tid == 0) {
                __threadfence();
                atomicAdd(cnt, 1u);
            }
        }
    }
}

// ---------------- FC head ----------------
__global__ __launch_bounds__(256) void fc_kernel(
    int stage, const float* __restrict__ W, const float* __restrict__ bias,
    float* __restrict__ dout) {
    __shared__ float As[32][33];
    __shared__ float Ws[32][33];
    const float* A; float* out; int K, N; int relu;
    if (stage == 0) { A = g_y0 + (size_t)76 * 65536; out = g_f1; K = 256; N = 512; relu = 1; }
    else if (stage == 1) { A = g_f1; out = g_f2; K = 512; N = 512; relu = 1; }
    else { A = g_f2; out = dout; K = 512; N = 256; relu = 0; }
    int n0 = blockIdx.x * 32, m0 = blockIdx.y * 32;
    int tid = threadIdx.x;
    int lrow = tid >> 3, lkq = tid & 7;
    int ty = tid >> 4, tx = tid & 15;
    float acc[2][2] = {{0.f, 0.f}, {0.f, 0.f}};
    for (int k0 = 0; k0 < K; k0 += 32) {
        __syncthreads();
        {
            float4 va = *(const float4*)&A[(size_t)(m0 + lrow) * K + k0 + 4 * lkq];
            As[lrow][4*lkq+0] = va.x; As[lrow][4*lkq+1] = va.y;
            As[lrow][4*lkq+2] = va.z; As[lrow][4*lkq+3] = va.w;
            float4 vw = *(const float4*)&W[(size_t)(n0 + lrow) * K + k0 + 4 * lkq];
            Ws[lrow][4*lkq+0] = vw.x; Ws[lrow][4*lkq+1] = vw.y;
            Ws[lrow][4*lkq+2] = vw.z; Ws[lrow][4*lkq+3] = vw.w;
        }
        __syncthreads();
        #pragma unroll
        for (int kk = 0; kk < 32; kk++) {
            float a0 = As[2*ty][kk], a1 = As[2*ty+1][kk];
            float w0 = Ws[2*tx][kk], w1 = Ws[2*tx+1][kk];
            acc[0][0] = fmaf(a0, w0, acc[0][0]);
            acc[0][1] = fmaf(a0, w1, acc[0][1]);
            acc[1][0] = fmaf(a1, w0, acc[1][0]);
            acc[1][1] = fmaf(a1, w1, acc[1][1]);
        }
    }
    #pragma unroll
    for (int i = 0; i < 2; i++) {
        #pragma unroll
        for (int j = 0; j < 2; j++) {
            int m = m0 + 2 * ty + i, n = n0 + 2 * tx + j;
            float v = acc[i][j] + bias[n];
            if (relu) v = fmaxf(v, 0.f);
            out[(size_t)m * N + n] = v;
        }
    }
}

// ---------------- launch ----------------
extern "C" void kernel_launch(void* const* d_in, const int* in_sizes, int n_in,
                              void* d_out, int out_size) {
    const float* x       = (const float*)d_in[0];
    const float* conv_w0 = (const float*)d_in[1];
    const float* conv_b0 = (const float*)d_in[2];
    const float* bn_g0   = (const float*)d_in[3];
    const float* bn_b0   = (const float*)d_in[4];
    const float* bn_m0   = (const float*)d_in[5];
    const float* bn_v0   = (const float*)d_in[6];
    const float* conv_w1 = (const float*)d_in[7];
    const float* conv_b1 = (const float*)d_in[8];
    const float* bn_g1   = (const float*)d_in[9];
    const float* bn_b1   = (const float*)d_in[10];
    const float* bn_m1   = (const float*)d_in[11];
    const float* bn_v1   = (const float*)d_in[12];
    const float* Wih0    = (const float*)d_in[13];
    const float* Whh0    = (const float*)d_in[14];
    const float* bih0    = (const float*)d_in[15];
    const float* bhh0    = (const float*)d_in[16];
    const float* Wih1    = (const float*)d_in[17];
    const float* Whh1    = (const float*)d_in[18];
    const float* bih1    = (const float*)d_in[19];
    const float* bhh1    = (const float*)d_in[20];
    const float* fc0_w   = (const float*)d_in[21];
    const float* fc0_b   = (const float*)d_in[22];
    const float* fc1_w   = (const float*)d_in[23];
    const float* fc1_b   = (const float*)d_in[24];
    const float* out_w   = (const float*)d_in[25];
    const float* out_b   = (const float*)d_in[26];
    float* out = (float*)d_out;

    cudaFuncSetAttribute(lstm_persist_kernel,
                         cudaFuncAttributeMaxDynamicSharedMemorySize, LSTM_SMEM);
    cudaFuncSetAttribute(conv1_kernel,
                         cudaFuncAttributeMaxDynamicSharedMemorySize, C1_SMEM);
    cudaFuncSetAttribute(gemm_xproj_kernel,
                         cudaFuncAttributeMaxDynamicSharedMemorySize, XP_SMEM);

    conv0_kernel<<<dim3(5, 256), 256>>>(x, conv_w0, conv_b0, bn_g0, bn_b0, bn_m0, bn_v0);
    conv1_kernel<<<dim3(5, 256), 256, C1_SMEM>>>(conv_w1, conv_b1, bn_g1, bn_b1, bn_m1, bn_v1);

    gemm_xproj_kernel<<<dim3(8, 154), 256, XP_SMEM>>>(0, Wih0, bih0, bhh0);
    lstm_persist_kernel<<<128, 512, LSTM_SMEM>>>(0, 0u, Whh0);

    gemm_xproj_kernel<<<dim3(8, 154), 256, XP_SMEM>>>(1, Wih1, bih1, bhh1);
    lstm_persist_kernel<<<128, 512, LSTM_SMEM>>>(1, 16u * 76u, Whh1);

    fc_kernel<<<dim3(16, 8), 256>>>(0, fc0_w, fc0_b, out);
    fc_kernel<<<dim3(16, 8), 256>>>(1, fc1_w, fc1_b, out);
    fc_kernel<<<dim3(8, 8), 256>>>(2, out_w, out_b, out);
}